// round 15
// baseline (speedup 1.0000x reference)
#include <cuda_runtime.h>
#include <cstdint>

// ---------------------------------------------------------------------------
// logits = (mean of 5 inverted-dropout passes of x) @ W^T + b
//   x: [32, 2048, 1024] f32   W: [3, 1024] f32   b: [3] f32   out: [32,2048,3]
//
// Masks reproduce JAX threefry2x32, jax_threefry_partitionable=True:
//   split(key(42), 5): child j = full block output, key (0,42), counter (0,j)
//   random_bits(k,32,shape): bits(i) = x0_out ^ x1_out, counter (0,i)
//   bernoulli(k,1-p): keep <=> bits < (ceil(f32(1-p)*2^23) << 9)  (u32 cmp)
//
// Perf design (R13): threefry rotate computed as the 64-bit product
// x1 * 2^d (IMAD.WIDE.U32 on the FMA pipe), with (lo|hi)^x0 fused into a
// single LOP3 on the ALU pipe. This moves the per-round SHF off the
// saturated ALU pipe (R12: alu=93.5%, fma=26.8%) and balances the two pipes.
// The multiplier constants are built from an opaque kernel argument (one=1)
// so ptxas cannot strength-reduce the multiply back into shifts.
// ---------------------------------------------------------------------------

#define NUM_D 1024
#define NUM_ROWS 65536   /* 32 * 2048 */

struct U2 { unsigned a, b; };

__host__ __device__ constexpr unsigned rotl32c(unsigned v, int d) {
    return (v << d) | (v >> (32 - d));
}

// constexpr threefry2x32 (20 rounds) — JAX-exact key schedule (host-side only).
constexpr U2 tf_const(unsigned k0, unsigned k1, unsigned x0, unsigned x1) {
    unsigned ks0 = k0, ks1 = k1, ks2 = k0 ^ k1 ^ 0x1BD11BDAu;
    x0 += ks0; x1 += ks1;
    const int RA[4] = {13, 15, 26, 6};
    const int RB[4] = {17, 29, 16, 24};
    for (int g = 0; g < 5; ++g) {
        const int* R = (g % 2 == 0) ? RA : RB;
        for (int i = 0; i < 4; ++i) {
            x0 += x1; x1 = rotl32c(x1, R[i]); x1 ^= x0;
        }
        switch (g) {
            case 0: x0 += ks1; x1 += ks2 + 1u; break;
            case 1: x0 += ks2; x1 += ks0 + 2u; break;
            case 2: x0 += ks0; x1 += ks1 + 3u; break;
            case 3: x0 += ks1; x1 += ks2 + 4u; break;
            case 4: x0 += ks2; x1 += ks0 + 5u; break;
        }
    }
    return {x0, x1};
}

// Partitionable split: child key j = full block output, counter (0, j).
constexpr U2 KEY0 = tf_const(0u, 42u, 0u, 0u);   // p = 0.1
constexpr U2 KEY1 = tf_const(0u, 42u, 0u, 1u);   // p = 0.2
constexpr U2 KEY2 = tf_const(0u, 42u, 0u, 2u);   // p = 0.3
constexpr U2 KEY3 = tf_const(0u, 42u, 0u, 3u);   // p = 0.4
constexpr U2 KEY4 = tf_const(0u, 42u, 0u, 4u);   // p = 0.5

constexpr unsigned thresh_bits(double p) {
    float cf = (float)(1.0 - p);
    double v = (double)cf * 8388608.0;   // * 2^23
    unsigned t = (unsigned)v;
    if ((double)t < v) t += 1u;
    return t << 9;
}
constexpr unsigned TA = thresh_bits(0.1);
constexpr unsigned TB = thresh_bits(0.2);
constexpr unsigned TC = thresh_bits(0.3);
constexpr unsigned TD = thresh_bits(0.4);
constexpr unsigned TE = thresh_bits(0.5);

constexpr float inv5(double p) {
    return (float)(0.2 / (double)((float)(1.0 - p)));
}
constexpr float IA = inv5(0.1);
constexpr float IB = inv5(0.2);
constexpr float IC = inv5(0.3);
constexpr float ID = inv5(0.4);
constexpr float IE = inv5(0.5);

// One threefry round: x0 += x1; x1 = rotl(x1,d) ^ x0.
// rotl via 64-bit multiply by 2^d: product = {lo = x1<<d, hi = x1>>(32-d)},
// then (lo | hi) ^ x0 is a single LOP3. 'mult' is runtime-opaque (kernel arg
// derived), forcing IMAD.WIDE.U32 on the FMA pipe instead of SHF on ALU.
#define TF_RND_M(x0, x1, mult)                                            \
    {                                                                     \
        x0 += x1;                                                         \
        unsigned long long _w = (unsigned long long)(x1) *                \
                                (unsigned long long)(mult);               \
        x1 = (((unsigned)_w) | ((unsigned)(_w >> 32))) ^ (x0);            \
    }

// Full 20-round block with counter (0,i); returns x0_out ^ x1_out.
__device__ __forceinline__ unsigned tf_xor(unsigned ks0, unsigned ks1, unsigned i,
                                           unsigned m13, unsigned m15,
                                           unsigned m26, unsigned m6,
                                           unsigned m17, unsigned m29,
                                           unsigned m16, unsigned m24) {
    const unsigned ks2 = ks0 ^ ks1 ^ 0x1BD11BDAu;
    unsigned x0 = ks0;       // hi counter = 0
    unsigned x1 = i + ks1;   // lo counter = flat element index
    TF_RND_M(x0, x1, m13) TF_RND_M(x0, x1, m15) TF_RND_M(x0, x1, m26) TF_RND_M(x0, x1, m6)
    x0 += ks1; x1 += ks2 + 1u;
    TF_RND_M(x0, x1, m17) TF_RND_M(x0, x1, m29) TF_RND_M(x0, x1, m16) TF_RND_M(x0, x1, m24)
    x0 += ks2; x1 += ks0 + 2u;
    TF_RND_M(x0, x1, m13) TF_RND_M(x0, x1, m15) TF_RND_M(x0, x1, m26) TF_RND_M(x0, x1, m6)
    x0 += ks0; x1 += ks1 + 3u;
    TF_RND_M(x0, x1, m17) TF_RND_M(x0, x1, m29) TF_RND_M(x0, x1, m16) TF_RND_M(x0, x1, m24)
    x0 += ks1; x1 += ks2 + 4u;
    TF_RND_M(x0, x1, m13) TF_RND_M(x0, x1, m15) TF_RND_M(x0, x1, m26) TF_RND_M(x0, x1, m6)
    x0 += ks2; x1 += ks0 + 5u;
    return x0 ^ x1;
}

// One CTA per (b,s) row. 256 threads, 4 columns/thread. Per column: 5
// independent threefry chains (ILP=5), integer compare masks, fused
// scale + 3-output GEMV accumulation.
__global__ void __launch_bounds__(256)
nbme_head_kernel(const float* __restrict__ x,
                 const float* __restrict__ W,
                 const float* __restrict__ bias,
                 float* __restrict__ out,
                 unsigned one) {            // == 1, opaque to ptxas
    const unsigned r   = blockIdx.x;        // 0 .. 65535
    const unsigned tid = threadIdx.x;

    // Opaque rotation multipliers: 2^d, built from the runtime 'one'.
    const unsigned m13 = one << 13, m15 = one << 15, m26 = one << 26, m6  = one << 6;
    const unsigned m17 = one << 17, m29 = one << 29, m16 = one << 16, m24 = one << 24;

    const float* __restrict__ xr = x + (size_t)r * NUM_D;
    const unsigned base_idx = r * (unsigned)NUM_D;   // flat index < 2^26

    float a0 = 0.f, a1 = 0.f, a2 = 0.f;

#pragma unroll 1
    for (int k = 0; k < 4; ++k) {
        const unsigned c = tid + (unsigned)k * 256u;

        // loads issued first — overlap with the integer chains
        const float xv = xr[c];
        const float w0 = __ldg(&W[c]);
        const float w1 = __ldg(&W[NUM_D + c]);
        const float w2 = __ldg(&W[2 * NUM_D + c]);

        const unsigned i = base_idx + c;

        const unsigned ma = tf_xor(KEY0.a, KEY0.b, i, m13, m15, m26, m6, m17, m29, m16, m24);
        const unsigned mb = tf_xor(KEY1.a, KEY1.b, i, m13, m15, m26, m6, m17, m29, m16, m24);
        const unsigned mc = tf_xor(KEY2.a, KEY2.b, i, m13, m15, m26, m6, m17, m29, m16, m24);
        const unsigned md = tf_xor(KEY3.a, KEY3.b, i, m13, m15, m26, m6, m17, m29, m16, m24);
        const unsigned me = tf_xor(KEY4.a, KEY4.b, i, m13, m15, m26, m6, m17, m29, m16, m24);

        float s = 0.f;
        if (ma < TA) s += IA;
        if (mb < TB) s += IB;
        if (mc < TC) s += IC;
        if (md < TD) s += ID;
        if (me < TE) s += IE;

        const float xs = xv * s;
        a0 = fmaf(xs, w0, a0);
        a1 = fmaf(xs, w1, a1);
        a2 = fmaf(xs, w2, a2);
    }

    // --- block reduction: 3 partial dots ---
    float vals[3] = {a0, a1, a2};
#pragma unroll
    for (int o = 0; o < 3; ++o) {
#pragma unroll
        for (int s = 16; s > 0; s >>= 1)
            vals[o] += __shfl_xor_sync(0xffffffffu, vals[o], s);
    }

    __shared__ float red[8][3];
    const unsigned warp = tid >> 5, lane = tid & 31;
    if (lane == 0) {
#pragma unroll
        for (int o = 0; o < 3; ++o) red[warp][o] = vals[o];
    }
    __syncthreads();

    if (tid < 3) {
        float v = 0.f;
#pragma unroll
        for (int w = 0; w < 8; ++w) v += red[w][tid];
        out[(size_t)r * 3 + tid] = v + __ldg(&bias[tid]);
    }
}

extern "C" void kernel_launch(void* const* d_in, const int* in_sizes, int n_in,
                              void* d_out, int out_size) {
    (void)in_sizes; (void)n_in; (void)out_size;
    const float* x  = (const float*)d_in[0];  // [32,2048,1024]
    const float* W  = (const float*)d_in[1];  // [3,1024]
    const float* b  = (const float*)d_in[2];  // [3]
    float* out      = (float*)d_out;          // [32,2048,3]

    nbme_head_kernel<<<NUM_ROWS, 256>>>(x, W, b, out, 1u);
}

// round 16
// speedup vs baseline: 1.2091x; 1.2091x over previous
#include <cuda_runtime.h>
#include <cstdint>

// ---------------------------------------------------------------------------
// logits = (mean of 5 inverted-dropout passes of x) @ W^T + b
//   x: [32, 2048, 1024] f32   W: [3, 1024] f32   b: [3] f32   out: [32,2048,3]
//
// Masks reproduce JAX threefry2x32, jax_threefry_partitionable=True:
//   split(key(42), 5): child j = full block output, key (0,42), counter (0,j)
//   random_bits(k,32,shape): bits(i) = x0_out ^ x1_out, counter (0,i)
//   bernoulli(k,1-p): keep <=> bits < (ceil(f32(1-p)*2^23) << 9)  (u32 cmp)
//
// Perf design (R16), calibrated on R12 (SHF, alu=93.5% wall, 834us) and R15
// (all-wide rotate regression: IMAD.WIDE ~2 fma slots + issue hazards):
//   * round adds x0+=x1 forced onto the FMA pipe via IMAD: x0 = x0*one + x1
//     ('one' is a runtime kernel arg == 1, opaque to ptxas)  [-~60 alu/elt]
//   * SPARSE hybrid rotate: only round 1 of each 4-round group (5/20 rounds,
//     d in {13,17}) rotates via the 64-bit product x1*2^d with (lo|hi)^x0
//     fused into one LOP3; the other 15 rounds keep SHF.     [-25 alu/elt]
//   Target: alu ~= fma ~= 180 ops/elt (vs 265 alu-bound in R12).
// ---------------------------------------------------------------------------

#define NUM_D 1024
#define NUM_ROWS 65536   /* 32 * 2048 */

struct U2 { unsigned a, b; };

__host__ __device__ constexpr unsigned rotl32c(unsigned v, int d) {
    return (v << d) | (v >> (32 - d));
}

// constexpr threefry2x32 (20 rounds) — JAX-exact key schedule (host-side only).
constexpr U2 tf_const(unsigned k0, unsigned k1, unsigned x0, unsigned x1) {
    unsigned ks0 = k0, ks1 = k1, ks2 = k0 ^ k1 ^ 0x1BD11BDAu;
    x0 += ks0; x1 += ks1;
    const int RA[4] = {13, 15, 26, 6};
    const int RB[4] = {17, 29, 16, 24};
    for (int g = 0; g < 5; ++g) {
        const int* R = (g % 2 == 0) ? RA : RB;
        for (int i = 0; i < 4; ++i) {
            x0 += x1; x1 = rotl32c(x1, R[i]); x1 ^= x0;
        }
        switch (g) {
            case 0: x0 += ks1; x1 += ks2 + 1u; break;
            case 1: x0 += ks2; x1 += ks0 + 2u; break;
            case 2: x0 += ks0; x1 += ks1 + 3u; break;
            case 3: x0 += ks1; x1 += ks2 + 4u; break;
            case 4: x0 += ks2; x1 += ks0 + 5u; break;
        }
    }
    return {x0, x1};
}

// Partitionable split: child key j = full block output, counter (0, j).
constexpr U2 KEY0 = tf_const(0u, 42u, 0u, 0u);   // p = 0.1
constexpr U2 KEY1 = tf_const(0u, 42u, 0u, 1u);   // p = 0.2
constexpr U2 KEY2 = tf_const(0u, 42u, 0u, 2u);   // p = 0.3
constexpr U2 KEY3 = tf_const(0u, 42u, 0u, 3u);   // p = 0.4
constexpr U2 KEY4 = tf_const(0u, 42u, 0u, 4u);   // p = 0.5

constexpr unsigned thresh_bits(double p) {
    float cf = (float)(1.0 - p);
    double v = (double)cf * 8388608.0;   // * 2^23
    unsigned t = (unsigned)v;
    if ((double)t < v) t += 1u;
    return t << 9;
}
constexpr unsigned TA = thresh_bits(0.1);
constexpr unsigned TB = thresh_bits(0.2);
constexpr unsigned TC = thresh_bits(0.3);
constexpr unsigned TD = thresh_bits(0.4);
constexpr unsigned TE = thresh_bits(0.5);

constexpr float inv5(double p) {
    return (float)(0.2 / (double)((float)(1.0 - p)));
}
constexpr float IA = inv5(0.1);
constexpr float IB = inv5(0.2);
constexpr float IC = inv5(0.3);
constexpr float ID = inv5(0.4);
constexpr float IE = inv5(0.5);

// SHF round: add forced to FMA pipe (IMAD via *one), rotate on ALU (SHF),
// xor on ALU (LOP3).
#define TF_RND_S(x0, x1, d)                                   \
    {                                                         \
        x0 = x0 * one + x1;                                   \
        x1 = __funnelshift_l(x1, x1, (d)) ^ x0;               \
    }

// Wide round: add on FMA (IMAD via *one), rotate on FMA (IMAD.WIDE by 2^d),
// (lo|hi)^x0 fused into a single LOP3 on ALU.
#define TF_RND_W(x0, x1, mult)                                \
    {                                                         \
        x0 = x0 * one + x1;                                   \
        unsigned long long _w = (unsigned long long)(x1) *    \
                                (unsigned long long)(mult);   \
        x1 = (((unsigned)_w) | ((unsigned)(_w >> 32))) ^ x0;  \
    }

// Full 20-round block with counter (0,i); returns x0_out ^ x1_out.
// First round of each 4-round group is wide (d = 13 or 17); rest are SHF.
__device__ __forceinline__ unsigned tf_xor(unsigned ks0, unsigned ks1, unsigned i,
                                           unsigned one,
                                           unsigned m13, unsigned m17) {
    const unsigned ks2 = ks0 ^ ks1 ^ 0x1BD11BDAu;
    unsigned x0 = ks0;       // hi counter = 0
    unsigned x1 = i + ks1;   // lo counter = flat element index
    TF_RND_W(x0, x1, m13) TF_RND_S(x0, x1, 15) TF_RND_S(x0, x1, 26) TF_RND_S(x0, x1, 6)
    x0 += ks1; x1 += ks2 + 1u;
    TF_RND_W(x0, x1, m17) TF_RND_S(x0, x1, 29) TF_RND_S(x0, x1, 16) TF_RND_S(x0, x1, 24)
    x0 += ks2; x1 += ks0 + 2u;
    TF_RND_W(x0, x1, m13) TF_RND_S(x0, x1, 15) TF_RND_S(x0, x1, 26) TF_RND_S(x0, x1, 6)
    x0 += ks0; x1 += ks1 + 3u;
    TF_RND_W(x0, x1, m17) TF_RND_S(x0, x1, 29) TF_RND_S(x0, x1, 16) TF_RND_S(x0, x1, 24)
    x0 += ks1; x1 += ks2 + 4u;
    TF_RND_W(x0, x1, m13) TF_RND_S(x0, x1, 15) TF_RND_S(x0, x1, 26) TF_RND_S(x0, x1, 6)
    x0 += ks2; x1 += ks0 + 5u;
    return x0 ^ x1;
}

// One CTA per (b,s) row. 256 threads, 4 columns/thread. Per column: 5
// independent threefry chains (ILP=5), integer compare masks, fused
// scale + 3-output GEMV accumulation.
__global__ void __launch_bounds__(256)
nbme_head_kernel(const float* __restrict__ x,
                 const float* __restrict__ W,
                 const float* __restrict__ bias,
                 float* __restrict__ out,
                 unsigned one) {            // == 1, opaque to ptxas
    const unsigned r   = blockIdx.x;        // 0 .. 65535
    const unsigned tid = threadIdx.x;

    // Opaque rotation multipliers (2 live registers only).
    const unsigned m13 = one << 13;
    const unsigned m17 = one << 17;

    const float* __restrict__ xr = x + (size_t)r * NUM_D;
    const unsigned base_idx = r * (unsigned)NUM_D;   // flat index < 2^26

    float a0 = 0.f, a1 = 0.f, a2 = 0.f;

#pragma unroll 1
    for (int k = 0; k < 4; ++k) {
        const unsigned c = tid + (unsigned)k * 256u;

        // loads issued first — overlap with the integer chains
        const float xv = xr[c];
        const float w0 = __ldg(&W[c]);
        const float w1 = __ldg(&W[NUM_D + c]);
        const float w2 = __ldg(&W[2 * NUM_D + c]);

        const unsigned i = base_idx + c;

        const unsigned ma = tf_xor(KEY0.a, KEY0.b, i, one, m13, m17);
        const unsigned mb = tf_xor(KEY1.a, KEY1.b, i, one, m13, m17);
        const unsigned mc = tf_xor(KEY2.a, KEY2.b, i, one, m13, m17);
        const unsigned md = tf_xor(KEY3.a, KEY3.b, i, one, m13, m17);
        const unsigned me = tf_xor(KEY4.a, KEY4.b, i, one, m13, m17);

        float s = 0.f;
        if (ma < TA) s += IA;
        if (mb < TB) s += IB;
        if (mc < TC) s += IC;
        if (md < TD) s += ID;
        if (me < TE) s += IE;

        const float xs = xv * s;
        a0 = fmaf(xs, w0, a0);
        a1 = fmaf(xs, w1, a1);
        a2 = fmaf(xs, w2, a2);
    }

    // --- block reduction: 3 partial dots ---
    float vals[3] = {a0, a1, a2};
#pragma unroll
    for (int o = 0; o < 3; ++o) {
#pragma unroll
        for (int s = 16; s > 0; s >>= 1)
            vals[o] += __shfl_xor_sync(0xffffffffu, vals[o], s);
    }

    __shared__ float red[8][3];
    const unsigned warp = tid >> 5, lane = tid & 31;
    if (lane == 0) {
#pragma unroll
        for (int o = 0; o < 3; ++o) red[warp][o] = vals[o];
    }
    __syncthreads();

    if (tid < 3) {
        float v = 0.f;
#pragma unroll
        for (int w = 0; w < 8; ++w) v += red[w][tid];
        out[(size_t)r * 3 + tid] = v + __ldg(&bias[tid]);
    }
}

extern "C" void kernel_launch(void* const* d_in, const int* in_sizes, int n_in,
                              void* d_out, int out_size) {
    (void)in_sizes; (void)n_in; (void)out_size;
    const float* x  = (const float*)d_in[0];  // [32,2048,1024]
    const float* W  = (const float*)d_in[1];  // [3,1024]
    const float* b  = (const float*)d_in[2];  // [3]
    float* out      = (float*)d_out;          // [32,2048,3]

    nbme_head_kernel<<<NUM_ROWS, 256>>>(x, W, b, out, 1u);
}

// round 17
// speedup vs baseline: 1.2495x; 1.0335x over previous
#include <cuda_runtime.h>
#include <cstdint>

// ---------------------------------------------------------------------------
// logits = (mean of 5 inverted-dropout passes of x) @ W^T + b
//   x: [32, 2048, 1024] f32   W: [3, 1024] f32   b: [3] f32   out: [32,2048,3]
//
// Masks reproduce JAX threefry2x32, jax_threefry_partitionable=True:
//   split(key(42), 5): child j = full block output, key (0,42), counter (0,j)
//   random_bits(k,32,shape): bits(i) = x0_out ^ x1_out, counter (0,i)
//   bernoulli(k,1-p): keep <=> bits < (ceil(f32(1-p)*2^23) << 9)  (u32 cmp)
//
// Perf lineage:
//   R12 (pure SHF rounds):            834us, alu=93.5% (wall), 6.5% bubble
//   R15 (all-wide rotate):           1058us, IMAD.WIDE=2 fma slots + hazards
//   R16 (x*one adds + 25 wide/elt):   875us, 22% bubble from 3-reg IMAD bank
//                                     conflicts + wide density
// R17 = R12 + wide rotate ONLY on the three d=13 rounds per block (15/elt,
// density 1-in-24), no add forcing (ptxas's natural IMAD.IADD-imm alternation
// is bank-conflict-free and already near-optimal). Moves 15 SHF/elt off the
// saturated ALU pipe at minimal scheduling risk: alu 210->195 forced ops/elt.
// ---------------------------------------------------------------------------

#define NUM_D 1024
#define NUM_ROWS 65536   /* 32 * 2048 */

struct U2 { unsigned a, b; };

__host__ __device__ constexpr unsigned rotl32c(unsigned v, int d) {
    return (v << d) | (v >> (32 - d));
}

// constexpr threefry2x32 (20 rounds) — JAX-exact key schedule (host-side only).
constexpr U2 tf_const(unsigned k0, unsigned k1, unsigned x0, unsigned x1) {
    unsigned ks0 = k0, ks1 = k1, ks2 = k0 ^ k1 ^ 0x1BD11BDAu;
    x0 += ks0; x1 += ks1;
    const int RA[4] = {13, 15, 26, 6};
    const int RB[4] = {17, 29, 16, 24};
    for (int g = 0; g < 5; ++g) {
        const int* R = (g % 2 == 0) ? RA : RB;
        for (int i = 0; i < 4; ++i) {
            x0 += x1; x1 = rotl32c(x1, R[i]); x1 ^= x0;
        }
        switch (g) {
            case 0: x0 += ks1; x1 += ks2 + 1u; break;
            case 1: x0 += ks2; x1 += ks0 + 2u; break;
            case 2: x0 += ks0; x1 += ks1 + 3u; break;
            case 3: x0 += ks1; x1 += ks2 + 4u; break;
            case 4: x0 += ks2; x1 += ks0 + 5u; break;
        }
    }
    return {x0, x1};
}

// Partitionable split: child key j = full block output, counter (0, j).
constexpr U2 KEY0 = tf_const(0u, 42u, 0u, 0u);   // p = 0.1
constexpr U2 KEY1 = tf_const(0u, 42u, 0u, 1u);   // p = 0.2
constexpr U2 KEY2 = tf_const(0u, 42u, 0u, 2u);   // p = 0.3
constexpr U2 KEY3 = tf_const(0u, 42u, 0u, 3u);   // p = 0.4
constexpr U2 KEY4 = tf_const(0u, 42u, 0u, 4u);   // p = 0.5

constexpr unsigned thresh_bits(double p) {
    float cf = (float)(1.0 - p);
    double v = (double)cf * 8388608.0;   // * 2^23
    unsigned t = (unsigned)v;
    if ((double)t < v) t += 1u;
    return t << 9;
}
constexpr unsigned TA = thresh_bits(0.1);
constexpr unsigned TB = thresh_bits(0.2);
constexpr unsigned TC = thresh_bits(0.3);
constexpr unsigned TD = thresh_bits(0.4);
constexpr unsigned TE = thresh_bits(0.5);

constexpr float inv5(double p) {
    return (float)(0.2 / (double)((float)(1.0 - p)));
}
constexpr float IA = inv5(0.1);
constexpr float IB = inv5(0.2);
constexpr float IC = inv5(0.3);
constexpr float ID = inv5(0.4);
constexpr float IE = inv5(0.5);

// Standard round: plain add (ptxas alternates IADD3 / IMAD.IADD-imm to
// balance pipes, bank-conflict-free), SHF rotate (alu), LOP3 xor (alu).
#define TF_RND_S(x0, x1, d)                                   \
    {                                                         \
        x0 += x1;                                             \
        x1 = __funnelshift_l(x1, x1, (d)) ^ x0;               \
    }

// Wide round (d=13 only): rotate via 64-bit product x1*2^13 (IMAD.WIDE.U32,
// fma pipe), (lo|hi)^x0 fused into one LOP3 (alu). Removes the SHF from the
// saturated alu pipe. 'm13' is runtime-opaque so ptxas can't strength-reduce.
#define TF_RND_W13(x0, x1)                                    \
    {                                                         \
        x0 += x1;                                             \
        unsigned long long _w = (unsigned long long)(x1) *    \
                                (unsigned long long)(m13);    \
        x1 = (((unsigned)_w) | ((unsigned)(_w >> 32))) ^ x0;  \
    }

// Full 20-round block with counter (0,i); returns x0_out ^ x1_out.
// d=13 rounds (first round of groups 0,2,4) use the wide-mul rotate.
__device__ __forceinline__ unsigned tf_xor(unsigned ks0, unsigned ks1, unsigned i,
                                           unsigned m13) {
    const unsigned ks2 = ks0 ^ ks1 ^ 0x1BD11BDAu;
    unsigned x0 = ks0;       // hi counter = 0
    unsigned x1 = i + ks1;   // lo counter = flat element index
    TF_RND_W13(x0, x1) TF_RND_S(x0, x1, 15) TF_RND_S(x0, x1, 26) TF_RND_S(x0, x1, 6)
    x0 += ks1; x1 += ks2 + 1u;
    TF_RND_S(x0, x1, 17) TF_RND_S(x0, x1, 29) TF_RND_S(x0, x1, 16) TF_RND_S(x0, x1, 24)
    x0 += ks2; x1 += ks0 + 2u;
    TF_RND_W13(x0, x1) TF_RND_S(x0, x1, 15) TF_RND_S(x0, x1, 26) TF_RND_S(x0, x1, 6)
    x0 += ks0; x1 += ks1 + 3u;
    TF_RND_S(x0, x1, 17) TF_RND_S(x0, x1, 29) TF_RND_S(x0, x1, 16) TF_RND_S(x0, x1, 24)
    x0 += ks1; x1 += ks2 + 4u;
    TF_RND_W13(x0, x1) TF_RND_S(x0, x1, 15) TF_RND_S(x0, x1, 26) TF_RND_S(x0, x1, 6)
    x0 += ks2; x1 += ks0 + 5u;
    return x0 ^ x1;
}

// One CTA per (b,s) row. 256 threads, 4 columns/thread. Per column: 5
// independent threefry chains (ILP=5), integer compare masks, fused
// scale + 3-output GEMV accumulation.
__global__ void __launch_bounds__(256)
nbme_head_kernel(const float* __restrict__ x,
                 const float* __restrict__ W,
                 const float* __restrict__ bias,
                 float* __restrict__ out,
                 unsigned one) {            // == 1, opaque to ptxas
    const unsigned r   = blockIdx.x;        // 0 .. 65535
    const unsigned tid = threadIdx.x;

    const unsigned m13 = one << 13;         // opaque 2^13 multiplier

    const float* __restrict__ xr = x + (size_t)r * NUM_D;
    const unsigned base_idx = r * (unsigned)NUM_D;   // flat index < 2^26

    float a0 = 0.f, a1 = 0.f, a2 = 0.f;

#pragma unroll 1
    for (int k = 0; k < 4; ++k) {
        const unsigned c = tid + (unsigned)k * 256u;

        // loads issued first — overlap with the integer chains
        const float xv = xr[c];
        const float w0 = __ldg(&W[c]);
        const float w1 = __ldg(&W[NUM_D + c]);
        const float w2 = __ldg(&W[2 * NUM_D + c]);

        const unsigned i = base_idx + c;

        const unsigned ma = tf_xor(KEY0.a, KEY0.b, i, m13);
        const unsigned mb = tf_xor(KEY1.a, KEY1.b, i, m13);
        const unsigned mc = tf_xor(KEY2.a, KEY2.b, i, m13);
        const unsigned md = tf_xor(KEY3.a, KEY3.b, i, m13);
        const unsigned me = tf_xor(KEY4.a, KEY4.b, i, m13);

        float s = 0.f;
        if (ma < TA) s += IA;
        if (mb < TB) s += IB;
        if (mc < TC) s += IC;
        if (md < TD) s += ID;
        if (me < TE) s += IE;

        const float xs = xv * s;
        a0 = fmaf(xs, w0, a0);
        a1 = fmaf(xs, w1, a1);
        a2 = fmaf(xs, w2, a2);
    }

    // --- block reduction: 3 partial dots ---
    float vals[3] = {a0, a1, a2};
#pragma unroll
    for (int o = 0; o < 3; ++o) {
#pragma unroll
        for (int s = 16; s > 0; s >>= 1)
            vals[o] += __shfl_xor_sync(0xffffffffu, vals[o], s);
    }

    __shared__ float red[8][3];
    const unsigned warp = tid >> 5, lane = tid & 31;
    if (lane == 0) {
#pragma unroll
        for (int o = 0; o < 3; ++o) red[warp][o] = vals[o];
    }
    __syncthreads();

    if (tid < 3) {
        float v = 0.f;
#pragma unroll
        for (int w = 0; w < 8; ++w) v += red[w][tid];
        out[(size_t)r * 3 + tid] = v + __ldg(&bias[tid]);
    }
}

extern "C" void kernel_launch(void* const* d_in, const int* in_sizes, int n_in,
                              void* d_out, int out_size) {
    (void)in_sizes; (void)n_in; (void)out_size;
    const float* x  = (const float*)d_in[0];  // [32,2048,1024]
    const float* W  = (const float*)d_in[1];  // [3,1024]
    const float* b  = (const float*)d_in[2];  // [3]
    float* out      = (float*)d_out;          // [32,2048,3]

    nbme_head_kernel<<<NUM_ROWS, 256>>>(x, W, b, out, 1u);
}